// round 1
// baseline (speedup 1.0000x reference)
#include <cuda_runtime.h>
#include <cstdint>
#include <cstddef>

#define BB 1024
#define TT 1024
#define NN 34
#define BPB 7                      // batches per block
#define FWD_THREADS (BPB * NN)     // 238 threads
#define FWD_BLOCKS  148            // exactly one block per SM

// Scratch: backpointers (u8, [b][t][j]) + final argmax per batch.
__device__ unsigned char g_bp[(size_t)BB * TT * NN];
__device__ int g_idx[BB];

__global__ __launch_bounds__(FWD_THREADS)
void viterbi_fwd(const float* __restrict__ feat,
                 const float* __restrict__ trans,
                 float* __restrict__ out)
{
    const int tid = threadIdx.x;
    const int bl  = tid / NN;      // local batch 0..6
    const int j   = tid % NN;      // state
    int b = blockIdx.x * BPB + bl;
    if (b >= BB) b = BB - 1;       // clamped threads redo batch 1023 (benign identical writes)

    __shared__ __align__(16) float sc[2][BPB][36];  // double-buffered scores, padded row
    __shared__ float tend[NN];                      // trans[END][*]
    __shared__ float fin[BPB][NN];

    // transition row j in registers
    float tr[NN];
#pragma unroll
    for (int k = 0; k < NN; k++) tr[k] = trans[j * NN + k];
    if (tid < NN) tend[tid] = trans[(NN - 1) * NN + tid];

    // init carry: NEG everywhere, 0 at START (= NN-2)
    sc[0][bl][j] = (j == NN - 2) ? 0.0f : -6969.0f;
    __syncthreads();

    const size_t fbase = (size_t)b * ((size_t)TT * NN) + j;
    float f = feat[fbase];                       // feat[b][0][j]
    const float* fp = feat + fbase + NN;
    unsigned char* bpp = g_bp + (size_t)b * ((size_t)TT * NN) + j;

    int cur = 0;
#pragma unroll 1
    for (int t = 0; t < TT; t++) {
        // prefetch next feat
        float fn = 0.0f;
        if (t < TT - 1) fn = __ldg(fp);
        fp += NN;

        // candidates: v[k] = (score[k] + feat[j]) + trans[j][k]  (XLA association)
        const float4* S4 = (const float4*)(&sc[cur][bl][0]);
        float m[NN];
#pragma unroll
        for (int i = 0; i < 8; i++) {
            float4 q = S4[i];
            m[4*i+0] = (q.x + f) + tr[4*i+0];
            m[4*i+1] = (q.y + f) + tr[4*i+1];
            m[4*i+2] = (q.z + f) + tr[4*i+2];
            m[4*i+3] = (q.w + f) + tr[4*i+3];
        }
        {
            float2 q = *(const float2*)(&sc[cur][bl][32]);
            m[32] = (q.x + f) + tr[32];
            m[33] = (q.y + f) + tr[33];
        }

        // tournament (max, argmax); >= keep-left preserves first-occurrence ties
        int idx[NN];
#pragma unroll
        for (int k = 0; k < NN; k++) idx[k] = k;
#pragma unroll
        for (int s = 1; s < NN; s <<= 1) {
#pragma unroll
            for (int k = 0; k + s < NN; k += (s << 1)) {
                float vb = m[k + s];
                bool p = m[k] >= vb;
                m[k]   = p ? m[k]   : vb;
                idx[k] = p ? idx[k] : idx[k + s];
            }
        }

        *bpp = (unsigned char)idx[0];
        bpp += NN;

        sc[cur ^ 1][bl][j] = m[0];   // new carry (feat already folded in)
        f = fn;
        cur ^= 1;
        __syncthreads();
    }

    // termination: + trans[END][j], then argmax over j (strict > = first occurrence)
    fin[bl][j] = sc[cur][bl][j] + tend[j];
    __syncthreads();
    if (j == 0) {
        float bm = -3.4e38f; int bi = 0;
#pragma unroll
        for (int k = 0; k < NN; k++) {
            float v = fin[bl][k];
            if (v > bm) { bm = v; bi = k; }
        }
        out[b] = bm;        // best score
        g_idx[b] = bi;      // final state
    }
}

__global__ __launch_bounds__(256)
void viterbi_back(float* __restrict__ out)
{
    __shared__ unsigned char bp[TT * NN];    // 34816 B
    const int b = blockIdx.x;

    const uint4* src = (const uint4*)(g_bp + (size_t)b * ((size_t)TT * NN));
    uint4* dst = (uint4*)bp;
    for (int i = threadIdx.x; i < (TT * NN) / 16; i += 256) dst[i] = src[i];
    __syncthreads();

    if (threadIdx.x == 0) {
        int i = g_idx[b];
        float* path = out + BB + (size_t)b * (TT + 1);
        path[TT] = (float)i;
        for (int t = TT - 1; t >= 0; t--) {
            i = bp[t * NN + i];
            path[t] = (float)i;
        }
    }
}

extern "C" void kernel_launch(void* const* d_in, const int* in_sizes, int n_in,
                              void* d_out, int out_size)
{
    const float* feat  = (const float*)d_in[0];
    const float* trans = (const float*)d_in[1];
    // defensive: identify transitions by its size (34*34 = 1156)
    if (n_in >= 2 && in_sizes[0] == NN * NN) {
        feat  = (const float*)d_in[1];
        trans = (const float*)d_in[0];
    }
    float* out = (float*)d_out;

    viterbi_fwd<<<FWD_BLOCKS, FWD_THREADS>>>(feat, trans, out);
    viterbi_back<<<BB, 256>>>(out);
}